// round 11
// baseline (speedup 1.0000x reference)
#include <cuda_runtime.h>
#include <math.h>

#define BATCH 4
#define CIN   64
#define COUT  64
#define H_    96
#define W_    320
#define HW    (H_ * W_)

typedef unsigned long long ull;

// packed f32x2 helpers (sm_100+)
#define FMA2(d, a, b) asm("fma.rn.f32x2 %0, %1, %2, %0;" : "+l"(d) : "l"(a), "l"(b))
__device__ __forceinline__ ull pack2(float lo, float hi) {
    ull r;
    asm("mov.b64 %0, {%1, %2};" : "=l"(r) : "f"(lo), "f"(hi));
    return r;
}
__device__ __forceinline__ void unpack2(ull v, float& lo, float& hi) {
    asm("mov.b64 {%0, %1}, %2;" : "=f"(lo), "=f"(hi) : "l"(v));
}

// ---------------- scratch (static device globals; no allocations) ----------
__device__ float g_buf[BATCH * 32];
__device__ float l_buf[BATCH * 32 * HW];
__device__ float off_buf[BATCH * 18 * HW];
__device__ float mask_buf[BATCH * 9 * HW];

// ---------------- Kernel A: tiny MLP for g (B x 32) ------------------------
__global__ void g_kernel(const float* __restrict__ scale,
                         const float* __restrict__ w1, const float* __restrict__ b1,
                         const float* __restrict__ w2, const float* __restrict__ b2)
{
    int tid = threadIdx.x;
    if (tid >= BATCH * 32) return;
    int b = tid >> 5;
    int i = tid & 31;
    const float* s = scale + b * 5;
    float bs0 = s[4] - s[2];
    float bs1 = s[3] - s[1];
    float acc = b2[i];
    for (int j = 0; j < 64; j++) {
        float h = fmaf(bs0, w1[j * 2 + 0], fmaf(bs1, w1[j * 2 + 1], b1[j]));
        h = fmaxf(h, 0.f);
        acc = fmaf(h, w2[i * 64 + j], acc);
    }
    g_buf[b * 32 + i] = acc;
}

// ---------------- Kernel B: merged loc conv + mask conv --------------------
// 160 threads, 2 adjacent px per thread. Shared input taps feed both convs.
// loc: conv3x3(64->32) + relu + 1x1(32->32) -> l_buf
// mask: conv3x3(64->9) + sigmoid -> mask_buf
__global__ void __launch_bounds__(160, 1) locmask_kernel(const float* __restrict__ x,
    const float* __restrict__ w1, const float* __restrict__ b1,
    const float* __restrict__ w2, const float* __restrict__ b2,
    const float* __restrict__ mw, const float* __restrict__ mb)
{
    __shared__ float ws[32 * 9 * 32];     // loc [cl][k][co]   36 KB
    __shared__ float wm[32 * 9 * 12];     // mask [cl][k][co pad12] 13.5 KB
    __shared__ float w2s[32 * 32];
    __shared__ float b1s[32], b2s[32], mbs[9];

    int tid = threadIdx.x;
    int bh  = blockIdx.x;
    int b   = bh / H_;
    int h   = bh % H_;
    int w0  = tid * 2;

    if (tid < 32) { b1s[tid] = b1[tid]; b2s[tid] = b2[tid]; }
    if (tid < 9)  mbs[tid] = mb[tid];
    for (int i = tid; i < 32 * 32; i += 160) w2s[i] = w2[i];

    ull acc0[16], acc1[16];        // loc accumulators (16 co-pairs x 2 px)
    ull ma0[6], ma1[6];            // mask accumulators (6 co-pairs x 2 px)
    #pragma unroll
    for (int j = 0; j < 16; j++) { acc0[j] = 0ull; acc1[j] = 0ull; }
    #pragma unroll
    for (int j = 0; j < 6; j++) { ma0[j] = 0ull; ma1[j] = 0ull; }

    for (int chunk = 0; chunk < 2; chunk++) {
        __syncthreads();
        for (int i = tid; i < 32 * 9 * 32; i += 160) {
            int co = i & 31;
            int t  = i >> 5;
            int k  = t % 9;
            int cl = t / 9;
            ws[i] = w1[(co * CIN + chunk * 32 + cl) * 9 + k];
        }
        for (int i = tid; i < 32 * 9 * 12; i += 160) {
            int co = i % 12;
            int t  = i / 12;
            int k  = t % 9;
            int cl = t / 9;
            wm[i] = (co < 9) ? mw[(co * CIN + chunk * 32 + cl) * 9 + k] : 0.f;
        }
        __syncthreads();

        for (int cl = 0; cl < 32; cl++) {
            const float* xp = x + (size_t)((b * CIN + chunk * 32 + cl) * HW);
            float m[3][4];
            #pragma unroll
            for (int r = 0; r < 3; r++) {
                int yy = h + r - 1;
                bool yok = (unsigned)yy < (unsigned)H_;
                #pragma unroll
                for (int c = 0; c < 4; c++) {
                    int xx = w0 + c - 1;
                    bool ok = yok && ((unsigned)xx < (unsigned)W_);
                    m[r][c] = ok ? __ldg(xp + yy * W_ + xx) : 0.f;
                }
            }
            #pragma unroll
            for (int k = 0; k < 9; k++) {
                int ky = k / 3, kx = k % 3;
                ull vp0 = pack2(m[ky][kx],     m[ky][kx]);
                ull vp1 = pack2(m[ky][kx + 1], m[ky][kx + 1]);

                // ---- stage loc weights (8 LDS.128), then FMA block ----
                const ulonglong2* wq = (const ulonglong2*)(ws + (cl * 9 + k) * 32);
                ull qr[16];
                #pragma unroll
                for (int j = 0; j < 8; j++) {
                    ulonglong2 t = wq[j];
                    qr[2 * j] = t.x; qr[2 * j + 1] = t.y;
                }
                #pragma unroll
                for (int j = 0; j < 16; j++) {
                    FMA2(acc0[j], vp0, qr[j]);
                    FMA2(acc1[j], vp1, qr[j]);
                }

                // ---- stage mask weights (3 LDS.128), then FMA block ----
                const ulonglong2* mq = (const ulonglong2*)(wm + (cl * 9 + k) * 12);
                ull mr[6];
                #pragma unroll
                for (int j = 0; j < 3; j++) {
                    ulonglong2 t = mq[j];
                    mr[2 * j] = t.x; mr[2 * j + 1] = t.y;
                }
                #pragma unroll
                for (int j = 0; j < 6; j++) {
                    FMA2(ma0[j], vp0, mr[j]);
                    FMA2(ma1[j], vp1, mr[j]);
                }
            }
        }
    }

    // mask epilogue: sigmoid
    {
        float r0[12], r1[12];
        #pragma unroll
        for (int j = 0; j < 6; j++) {
            unpack2(ma0[j], r0[2 * j], r0[2 * j + 1]);
            unpack2(ma1[j], r1[2 * j], r1[2 * j + 1]);
        }
        int mbase = b * 9 * HW + h * W_ + w0;
        #pragma unroll
        for (int co = 0; co < 9; co++) {
            float s0 = r0[co] + mbs[co];
            float s1 = r1[co] + mbs[co];
            *(float2*)(mask_buf + mbase + co * HW) =
                make_float2(1.f / (1.f + expf(-s0)), 1.f / (1.f + expf(-s1)));
        }
    }

    // loc epilogue: relu + 1x1
    float a0[32], a1[32];
    #pragma unroll
    for (int j = 0; j < 16; j++) {
        float lo, hi;
        unpack2(acc0[j], lo, hi);
        a0[2 * j]     = fmaxf(lo + b1s[2 * j], 0.f);
        a0[2 * j + 1] = fmaxf(hi + b1s[2 * j + 1], 0.f);
        unpack2(acc1[j], lo, hi);
        a1[2 * j]     = fmaxf(lo + b1s[2 * j], 0.f);
        a1[2 * j + 1] = fmaxf(hi + b1s[2 * j + 1], 0.f);
    }
    int base = b * 32 * HW + h * W_ + w0;
    for (int c2 = 0; c2 < 32; c2++) {
        float s0 = b2s[c2], s1 = s0;
        const float* wp = w2s + c2 * 32;
        #pragma unroll
        for (int c1 = 0; c1 < 32; c1++) {
            float wv = wp[c1];
            s0 = fmaf(a0[c1], wv, s0);
            s1 = fmaf(a1[c1], wv, s1);
        }
        *(float2*)(l_buf + base + c2 * HW) = make_float2(s0, s1);
    }
}

// ---------------- Kernel C: fuse conv3x3(cat(g,l)->32,relu) + 1x1(32->18) --
__global__ void __launch_bounds__(160, 1) fuse_kernel(
    const float* __restrict__ w1, const float* __restrict__ b1,
    const float* __restrict__ w2, const float* __restrict__ b2)
{
    __shared__ float ws[32 * 9 * 32];
    __shared__ float w2s[18 * 32];
    __shared__ float gs[32];
    __shared__ float b1s[32], b2s[18];

    int tid = threadIdx.x;
    int bh  = blockIdx.x;
    int b   = bh / H_;
    int h   = bh % H_;
    int w0  = tid * 2;

    if (tid < 32) { b1s[tid] = b1[tid]; gs[tid] = g_buf[b * 32 + tid]; }
    if (tid < 18) b2s[tid] = b2[tid];
    for (int i = tid; i < 18 * 32; i += 160) w2s[i] = w2[i];

    ull acc0[16], acc1[16];
    #pragma unroll
    for (int j = 0; j < 16; j++) { acc0[j] = 0ull; acc1[j] = 0ull; }

    for (int chunk = 0; chunk < 2; chunk++) {
        __syncthreads();
        for (int i = tid; i < 32 * 9 * 32; i += 160) {
            int co = i & 31;
            int t  = i >> 5;
            int k  = t % 9;
            int cl = t / 9;
            ws[i] = w1[(co * 64 + chunk * 32 + cl) * 9 + k];
        }
        __syncthreads();

        for (int cl = 0; cl < 32; cl++) {
            float m[3][4];
            if (chunk == 0) {
                float gv = gs[cl];
                #pragma unroll
                for (int r = 0; r < 3; r++) {
                    int yy = h + r - 1;
                    bool yok = (unsigned)yy < (unsigned)H_;
                    #pragma unroll
                    for (int c = 0; c < 4; c++) {
                        int xx = w0 + c - 1;
                        bool ok = yok && ((unsigned)xx < (unsigned)W_);
                        m[r][c] = ok ? gv : 0.f;
                    }
                }
            } else {
                const float* xp = l_buf + (size_t)((b * 32 + cl) * HW);
                #pragma unroll
                for (int r = 0; r < 3; r++) {
                    int yy = h + r - 1;
                    bool yok = (unsigned)yy < (unsigned)H_;
                    #pragma unroll
                    for (int c = 0; c < 4; c++) {
                        int xx = w0 + c - 1;
                        bool ok = yok && ((unsigned)xx < (unsigned)W_);
                        m[r][c] = ok ? __ldg(xp + yy * W_ + xx) : 0.f;
                    }
                }
            }
            #pragma unroll
            for (int k = 0; k < 9; k++) {
                int ky = k / 3, kx = k % 3;
                ull vp0 = pack2(m[ky][kx],     m[ky][kx]);
                ull vp1 = pack2(m[ky][kx + 1], m[ky][kx + 1]);
                const ulonglong2* wq = (const ulonglong2*)(ws + (cl * 9 + k) * 32);
                ull qr[16];
                #pragma unroll
                for (int j = 0; j < 8; j++) {
                    ulonglong2 t = wq[j];
                    qr[2 * j] = t.x; qr[2 * j + 1] = t.y;
                }
                #pragma unroll
                for (int j = 0; j < 16; j++) {
                    FMA2(acc0[j], vp0, qr[j]);
                    FMA2(acc1[j], vp1, qr[j]);
                }
            }
        }
    }

    float a0[32], a1[32];
    #pragma unroll
    for (int j = 0; j < 16; j++) {
        float lo, hi;
        unpack2(acc0[j], lo, hi);
        a0[2 * j]     = fmaxf(lo + b1s[2 * j], 0.f);
        a0[2 * j + 1] = fmaxf(hi + b1s[2 * j + 1], 0.f);
        unpack2(acc1[j], lo, hi);
        a1[2 * j]     = fmaxf(lo + b1s[2 * j], 0.f);
        a1[2 * j + 1] = fmaxf(hi + b1s[2 * j + 1], 0.f);
    }

    int base = b * 18 * HW + h * W_ + w0;
    for (int c2 = 0; c2 < 18; c2++) {
        float s0 = b2s[c2], s1 = s0;
        const float* wp = w2s + c2 * 32;
        #pragma unroll
        for (int c1 = 0; c1 < 32; c1++) {
            float wv = wp[c1];
            s0 = fmaf(a0[c1], wv, s0);
            s1 = fmaf(a1[c1], wv, s1);
        }
        *(float2*)(off_buf + base + c2 * HW) = make_float2(s0, s1);
    }
}

// ---------------- Kernel E: modulated deformable conv (64->64, 3x3) --------
// 160 threads, 2 adjacent px per thread, all 64 couts, staged weight loads.
__global__ void __launch_bounds__(160, 1) deform_kernel(const float* __restrict__ x,
    const float* __restrict__ wgt, const float* __restrict__ bias,
    float* __restrict__ out)
{
    __shared__ float ws[16 * 9 * 64];    // [cl][k][co]  36 KB
    __shared__ float cbs[64];

    int tid = threadIdx.x;
    int bh  = blockIdx.x;
    int b   = bh / H_;
    int h   = bh % H_;
    int w0  = tid * 2;

    if (tid < 64) cbs[tid] = bias[tid];
    __syncthreads();

    ull acc0[32], acc1[32];
    #pragma unroll
    for (int j = 0; j < 32; j++) {
        ull bp = pack2(cbs[2 * j], cbs[2 * j + 1]);
        acc0[j] = bp;
        acc1[j] = bp;
    }

    const float* offp = off_buf + (size_t)(b * 18 * HW) + h * W_ + w0;
    const float* mp   = mask_buf + (size_t)(b * 9 * HW) + h * W_ + w0;
    const float* xb   = x + (size_t)(b * CIN * HW);

    for (int chunk = 0; chunk < 4; chunk++) {
        __syncthreads();
        for (int i = tid; i < 16 * 9 * 64; i += 160) {
            int co = i & 63;
            int t  = i >> 6;
            int k  = t % 9;
            int cl = t / 9;
            ws[i] = wgt[(co * 64 + chunk * 16 + cl) * 9 + k];
        }
        __syncthreads();

        #pragma unroll
        for (int k = 0; k < 9; k++) {
            int ky = k / 3 - 1;
            int kx = k % 3 - 1;
            float dy0 = __ldg(offp + (k * 2 + 0) * HW);
            float dx0 = __ldg(offp + (k * 2 + 1) * HW);
            float mm0 = __ldg(mp + k * HW);
            float dy1 = __ldg(offp + (k * 2 + 0) * HW + 1);
            float dx1 = __ldg(offp + (k * 2 + 1) * HW + 1);
            float mm1 = __ldg(mp + k * HW + 1);

            // pixel 0 tap descriptors
            float ys0 = (float)(h + ky) + dy0;
            float xs0 = (float)(w0 + kx) + dx0;
            float fy0 = floorf(ys0), fx0 = floorf(xs0);
            int   y0a = (int)fy0,    x0a = (int)fx0;
            float wy0 = ys0 - fy0,   wx0 = xs0 - fx0;
            bool vy0a = (unsigned)y0a < (unsigned)H_;
            bool vy0b = (unsigned)(y0a + 1) < (unsigned)H_;
            bool vx0a = (unsigned)x0a < (unsigned)W_;
            bool vx0b = (unsigned)(x0a + 1) < (unsigned)W_;
            int y0c = min(max(y0a, 0), H_ - 1), y0d = min(max(y0a + 1, 0), H_ - 1);
            int x0c = min(max(x0a, 0), W_ - 1), x0d = min(max(x0a + 1, 0), W_ - 1);
            float a00 = (vy0a && vx0a) ? (1.f - wy0) * (1.f - wx0) * mm0 : 0.f;
            float a01 = (vy0a && vx0b) ? (1.f - wy0) * wx0 * mm0 : 0.f;
            float a10 = (vy0b && vx0a) ? wy0 * (1.f - wx0) * mm0 : 0.f;
            float a11 = (vy0b && vx0b) ? wy0 * wx0 * mm0 : 0.f;
            int p00 = y0c * W_ + x0c, p01 = y0c * W_ + x0d;
            int p10 = y0d * W_ + x0c, p11 = y0d * W_ + x0d;

            // pixel 1 tap descriptors
            float ys1 = (float)(h + ky) + dy1;
            float xs1 = (float)(w0 + 1 + kx) + dx1;
            float fy1 = floorf(ys1), fx1 = floorf(xs1);
            int   y1a = (int)fy1,    x1a = (int)fx1;
            float wy1 = ys1 - fy1,   wx1 = xs1 - fx1;
            bool vy1a = (unsigned)y1a < (unsigned)H_;
            bool vy1b = (unsigned)(y1a + 1) < (unsigned)H_;
            bool vx1a = (unsigned)x1a < (unsigned)W_;
            bool vx1b = (unsigned)(x1a + 1) < (unsigned)W_;
            int y1c = min(max(y1a, 0), H_ - 1), y1d = min(max(y1a + 1, 0), H_ - 1);
            int x1c = min(max(x1a, 0), W_ - 1), x1d = min(max(x1a + 1, 0), W_ - 1);
            float b00 = (vy1a && vx1a) ? (1.f - wy1) * (1.f - wx1) * mm1 : 0.f;
            float b01 = (vy1a && vx1b) ? (1.f - wy1) * wx1 * mm1 : 0.f;
            float b10 = (vy1b && vx1a) ? wy1 * (1.f - wx1) * mm1 : 0.f;
            float b11 = (vy1b && vx1b) ? wy1 * wx1 * mm1 : 0.f;
            int q00 = y1c * W_ + x1c, q01 = y1c * W_ + x1d;
            int q10 = y1d * W_ + x1c, q11 = y1d * W_ + x1d;

            #pragma unroll 2
            for (int cl = 0; cl < 16; cl++) {
                const float* xp = xb + (size_t)((chunk * 16 + cl) * HW);
                float t00 = __ldg(xp + p00);
                float t01 = __ldg(xp + p01);
                float t10 = __ldg(xp + p10);
                float t11 = __ldg(xp + p11);
                float u00 = __ldg(xp + q00);
                float u01 = __ldg(xp + q01);
                float u10 = __ldg(xp + q10);
                float u11 = __ldg(xp + q11);
                float v0 = a00 * t00;
                v0 = fmaf(a01, t01, v0);
                v0 = fmaf(a10, t10, v0);
                v0 = fmaf(a11, t11, v0);
                float v1 = b00 * u00;
                v1 = fmaf(b01, u01, v1);
                v1 = fmaf(b10, u10, v1);
                v1 = fmaf(b11, u11, v1);
                ull vp0 = pack2(v0, v0);
                ull vp1 = pack2(v1, v1);
                const ulonglong2* wq = (const ulonglong2*)(ws + (cl * 9 + k) * 64);
                // two staged groups of 8 LDS.128 each
                #pragma unroll
                for (int g = 0; g < 2; g++) {
                    ull qr[16];
                    #pragma unroll
                    for (int j = 0; j < 8; j++) {
                        ulonglong2 t = wq[g * 8 + j];
                        qr[2 * j] = t.x; qr[2 * j + 1] = t.y;
                    }
                    #pragma unroll
                    for (int j = 0; j < 16; j++) {
                        FMA2(acc0[g * 16 + j], vp0, qr[j]);
                        FMA2(acc1[g * 16 + j], vp1, qr[j]);
                    }
                }
            }
        }
    }

    int base = b * COUT * HW + h * W_ + w0;
    #pragma unroll
    for (int j = 0; j < 32; j++) {
        float l0, h0, l1, h1;
        unpack2(acc0[j], l0, h0);
        unpack2(acc1[j], l1, h1);
        *(float2*)(out + base + (2 * j) * HW)     = make_float2(l0, l1);
        *(float2*)(out + base + (2 * j + 1) * HW) = make_float2(h0, h1);
    }
}

// ---------------- launch ----------------------------------------------------
extern "C" void kernel_launch(void* const* d_in, const int* in_sizes, int n_in,
                              void* d_out, int out_size)
{
    const float* x        = (const float*)d_in[0];
    const float* scale    = (const float*)d_in[1];
    const float* glob_w1  = (const float*)d_in[2];
    const float* glob_b1  = (const float*)d_in[3];
    const float* glob_w2  = (const float*)d_in[4];
    const float* glob_b2  = (const float*)d_in[5];
    const float* loc_w1   = (const float*)d_in[6];
    const float* loc_b1   = (const float*)d_in[7];
    const float* loc_w2   = (const float*)d_in[8];
    const float* loc_b2   = (const float*)d_in[9];
    const float* fuse_w1  = (const float*)d_in[10];
    const float* fuse_b1  = (const float*)d_in[11];
    const float* fuse_w2  = (const float*)d_in[12];
    const float* fuse_b2  = (const float*)d_in[13];
    const float* mask_w   = (const float*)d_in[14];
    const float* mask_b   = (const float*)d_in[15];
    const float* conv_w   = (const float*)d_in[16];
    const float* conv_b   = (const float*)d_in[17];
    float* out = (float*)d_out;

    g_kernel<<<1, 128>>>(scale, glob_w1, glob_b1, glob_w2, glob_b2);
    locmask_kernel<<<BATCH * H_, 160>>>(x, loc_w1, loc_b1, loc_w2, loc_b2,
                                        mask_w, mask_b);
    fuse_kernel<<<BATCH * H_, 160>>>(fuse_w1, fuse_b1, fuse_w2, fuse_b2);
    deform_kernel<<<BATCH * H_, 160>>>(x, conv_w, conv_b, out);
}

// round 15
// speedup vs baseline: 1.4044x; 1.4044x over previous
#include <cuda_runtime.h>
#include <math.h>

#define BATCH 4
#define CIN   64
#define COUT  64
#define H_    96
#define W_    320
#define HW    (H_ * W_)

typedef unsigned long long ull;

// packed f32x2 helpers (sm_100+)
#define FMA2(d, a, b) asm("fma.rn.f32x2 %0, %1, %2, %0;" : "+l"(d) : "l"(a), "l"(b))
__device__ __forceinline__ ull pack2(float lo, float hi) {
    ull r;
    asm("mov.b64 %0, {%1, %2};" : "=l"(r) : "f"(lo), "f"(hi));
    return r;
}
__device__ __forceinline__ void unpack2(ull v, float& lo, float& hi) {
    asm("mov.b64 {%0, %1}, %2;" : "=f"(lo), "=f"(hi) : "l"(v));
}

// ---------------- scratch (static device globals; no allocations) ----------
__device__ float g_buf[BATCH * 32];
__device__ float l_buf[BATCH * 32 * HW];
__device__ float off_buf[BATCH * 18 * HW];
__device__ float mask_buf[BATCH * 9 * HW];
__device__ __align__(256) float convw_t[9 * 64 * 64];   // [k][ci][co]

// ---------------- prep: transpose deform weights ---------------------------
__global__ void prep_kernel(const float* __restrict__ conv_w)
{
    int i = blockIdx.x * blockDim.x + threadIdx.x;
    if (i < 9 * 64 * 64) {
        int co = i & 63;
        int ci = (i >> 6) & 63;
        int k  = i >> 12;
        convw_t[i] = conv_w[(co * 64 + ci) * 9 + k];
    }
}

// ---------------- Kernel A: tiny MLP for g (B x 32) ------------------------
__global__ void g_kernel(const float* __restrict__ scale,
                         const float* __restrict__ w1, const float* __restrict__ b1,
                         const float* __restrict__ w2, const float* __restrict__ b2)
{
    int tid = threadIdx.x;
    if (tid >= BATCH * 32) return;
    int b = tid >> 5;
    int i = tid & 31;
    const float* s = scale + b * 5;
    float bs0 = s[4] - s[2];
    float bs1 = s[3] - s[1];
    float acc = b2[i];
    for (int j = 0; j < 64; j++) {
        float h = fmaf(bs0, w1[j * 2 + 0], fmaf(bs1, w1[j * 2 + 1], b1[j]));
        h = fmaxf(h, 0.f);
        acc = fmaf(h, w2[i * 64 + j], acc);
    }
    g_buf[b * 32 + i] = acc;
}

// ---------------- Kernel B: loc conv3x3(64->32,relu) + conv1x1(32->32) -----
// 160 threads, 2 adjacent pixels per thread. (best-measured R8 form)
__global__ void __launch_bounds__(160) loc_kernel(const float* __restrict__ x,
    const float* __restrict__ w1, const float* __restrict__ b1,
    const float* __restrict__ w2, const float* __restrict__ b2)
{
    __shared__ float ws[32 * 9 * 32];     // [cin_local][k][cout]  36 KB
    __shared__ float w2s[32 * 32];
    __shared__ float b1s[32], b2s[32];

    int tid = threadIdx.x;
    int bh  = blockIdx.x;
    int b   = bh / H_;
    int h   = bh % H_;
    int w0  = tid * 2;

    if (tid < 32) { b1s[tid] = b1[tid]; b2s[tid] = b2[tid]; }
    for (int i = tid; i < 32 * 32; i += 160) w2s[i] = w2[i];

    ull acc0[16], acc1[16];
    #pragma unroll
    for (int j = 0; j < 16; j++) { acc0[j] = 0ull; acc1[j] = 0ull; }

    for (int chunk = 0; chunk < 2; chunk++) {
        __syncthreads();
        for (int i = tid; i < 32 * 9 * 32; i += 160) {
            int co = i & 31;
            int t  = i >> 5;
            int k  = t % 9;
            int cl = t / 9;
            ws[i] = w1[(co * CIN + chunk * 32 + cl) * 9 + k];
        }
        __syncthreads();

        for (int cl = 0; cl < 32; cl++) {
            const float* xp = x + (size_t)((b * CIN + chunk * 32 + cl) * HW);
            float m[3][4];
            #pragma unroll
            for (int r = 0; r < 3; r++) {
                int yy = h + r - 1;
                bool yok = (unsigned)yy < (unsigned)H_;
                #pragma unroll
                for (int c = 0; c < 4; c++) {
                    int xx = w0 + c - 1;
                    bool ok = yok && ((unsigned)xx < (unsigned)W_);
                    m[r][c] = ok ? __ldg(xp + yy * W_ + xx) : 0.f;
                }
            }
            #pragma unroll
            for (int k = 0; k < 9; k++) {
                int ky = k / 3, kx = k % 3;
                ull vp0 = pack2(m[ky][kx],     m[ky][kx]);
                ull vp1 = pack2(m[ky][kx + 1], m[ky][kx + 1]);
                const ulonglong2* wq = (const ulonglong2*)(ws + (cl * 9 + k) * 32);
                #pragma unroll
                for (int j = 0; j < 8; j++) {
                    ulonglong2 q = wq[j];
                    FMA2(acc0[2 * j],     vp0, q.x);
                    FMA2(acc0[2 * j + 1], vp0, q.y);
                    FMA2(acc1[2 * j],     vp1, q.x);
                    FMA2(acc1[2 * j + 1], vp1, q.y);
                }
            }
        }
    }

    float a0[32], a1[32];
    #pragma unroll
    for (int j = 0; j < 16; j++) {
        float lo, hi;
        unpack2(acc0[j], lo, hi);
        a0[2 * j]     = fmaxf(lo + b1s[2 * j], 0.f);
        a0[2 * j + 1] = fmaxf(hi + b1s[2 * j + 1], 0.f);
        unpack2(acc1[j], lo, hi);
        a1[2 * j]     = fmaxf(lo + b1s[2 * j], 0.f);
        a1[2 * j + 1] = fmaxf(hi + b1s[2 * j + 1], 0.f);
    }

    int base = b * 32 * HW + h * W_ + w0;
    for (int c2 = 0; c2 < 32; c2++) {
        float s0 = b2s[c2], s1 = b2s[c2];
        const float* wp = w2s + c2 * 32;
        #pragma unroll
        for (int c1 = 0; c1 < 32; c1++) {
            float wv = wp[c1];
            s0 = fmaf(a0[c1], wv, s0);
            s1 = fmaf(a1[c1], wv, s1);
        }
        l_buf[base + c2 * HW]     = s0;
        l_buf[base + c2 * HW + 1] = s1;
    }
}

// ---------------- Kernel C: fuse conv3x3(cat(g,l)->32,relu) + 1x1(32->18) --
__global__ void __launch_bounds__(160) fuse_kernel(
    const float* __restrict__ w1, const float* __restrict__ b1,
    const float* __restrict__ w2, const float* __restrict__ b2)
{
    __shared__ float ws[32 * 9 * 32];
    __shared__ float w2s[18 * 32];
    __shared__ float gs[32];
    __shared__ float b1s[32], b2s[18];

    int tid = threadIdx.x;
    int bh  = blockIdx.x;
    int b   = bh / H_;
    int h   = bh % H_;
    int w0  = tid * 2;

    if (tid < 32) { b1s[tid] = b1[tid]; gs[tid] = g_buf[b * 32 + tid]; }
    if (tid < 18) b2s[tid] = b2[tid];
    for (int i = tid; i < 18 * 32; i += 160) w2s[i] = w2[i];

    ull acc0[16], acc1[16];
    #pragma unroll
    for (int j = 0; j < 16; j++) { acc0[j] = 0ull; acc1[j] = 0ull; }

    for (int chunk = 0; chunk < 2; chunk++) {
        __syncthreads();
        for (int i = tid; i < 32 * 9 * 32; i += 160) {
            int co = i & 31;
            int t  = i >> 5;
            int k  = t % 9;
            int cl = t / 9;
            ws[i] = w1[(co * 64 + chunk * 32 + cl) * 9 + k];
        }
        __syncthreads();

        for (int cl = 0; cl < 32; cl++) {
            float m[3][4];
            if (chunk == 0) {
                float gv = gs[cl];
                #pragma unroll
                for (int r = 0; r < 3; r++) {
                    int yy = h + r - 1;
                    bool yok = (unsigned)yy < (unsigned)H_;
                    #pragma unroll
                    for (int c = 0; c < 4; c++) {
                        int xx = w0 + c - 1;
                        bool ok = yok && ((unsigned)xx < (unsigned)W_);
                        m[r][c] = ok ? gv : 0.f;
                    }
                }
            } else {
                const float* xp = l_buf + (size_t)((b * 32 + cl) * HW);
                #pragma unroll
                for (int r = 0; r < 3; r++) {
                    int yy = h + r - 1;
                    bool yok = (unsigned)yy < (unsigned)H_;
                    #pragma unroll
                    for (int c = 0; c < 4; c++) {
                        int xx = w0 + c - 1;
                        bool ok = yok && ((unsigned)xx < (unsigned)W_);
                        m[r][c] = ok ? __ldg(xp + yy * W_ + xx) : 0.f;
                    }
                }
            }
            #pragma unroll
            for (int k = 0; k < 9; k++) {
                int ky = k / 3, kx = k % 3;
                ull vp0 = pack2(m[ky][kx],     m[ky][kx]);
                ull vp1 = pack2(m[ky][kx + 1], m[ky][kx + 1]);
                const ulonglong2* wq = (const ulonglong2*)(ws + (cl * 9 + k) * 32);
                #pragma unroll
                for (int j = 0; j < 8; j++) {
                    ulonglong2 q = wq[j];
                    FMA2(acc0[2 * j],     vp0, q.x);
                    FMA2(acc0[2 * j + 1], vp0, q.y);
                    FMA2(acc1[2 * j],     vp1, q.x);
                    FMA2(acc1[2 * j + 1], vp1, q.y);
                }
            }
        }
    }

    float a0[32], a1[32];
    #pragma unroll
    for (int j = 0; j < 16; j++) {
        float lo, hi;
        unpack2(acc0[j], lo, hi);
        a0[2 * j]     = fmaxf(lo + b1s[2 * j], 0.f);
        a0[2 * j + 1] = fmaxf(hi + b1s[2 * j + 1], 0.f);
        unpack2(acc1[j], lo, hi);
        a1[2 * j]     = fmaxf(lo + b1s[2 * j], 0.f);
        a1[2 * j + 1] = fmaxf(hi + b1s[2 * j + 1], 0.f);
    }

    int base = b * 18 * HW + h * W_ + w0;
    for (int c2 = 0; c2 < 18; c2++) {
        float s0 = b2s[c2], s1 = b2s[c2];
        const float* wp = w2s + c2 * 32;
        #pragma unroll
        for (int c1 = 0; c1 < 32; c1++) {
            float wv = wp[c1];
            s0 = fmaf(a0[c1], wv, s0);
            s1 = fmaf(a1[c1], wv, s1);
        }
        off_buf[base + c2 * HW]     = s0;
        off_buf[base + c2 * HW + 1] = s1;
    }
}

// ---------------- Kernel D: mask conv3x3(64->9) + sigmoid ------------------
__global__ void __launch_bounds__(160) mask_kernel(const float* __restrict__ x,
    const float* __restrict__ wgt, const float* __restrict__ bias)
{
    __shared__ float ws[64 * 9 * 10];    // [cin][k][cout(pad10)]  23 KB
    __shared__ float bs[9];

    int tid = threadIdx.x;
    int bh  = blockIdx.x;
    int b   = bh / H_;
    int h   = bh % H_;
    int w0  = tid * 2;

    if (tid < 9) bs[tid] = bias[tid];
    for (int i = tid; i < 64 * 9 * 10; i += 160) {
        int co = i % 10;
        int t  = i / 10;
        int k  = t % 9;
        int ci = t / 9;
        ws[i] = (co < 9) ? wgt[(co * 64 + ci) * 9 + k] : 0.f;
    }
    __syncthreads();

    ull acc0[5], acc1[5];
    #pragma unroll
    for (int j = 0; j < 5; j++) { acc0[j] = 0ull; acc1[j] = 0ull; }

    for (int ci = 0; ci < 64; ci++) {
        const float* xp = x + (size_t)((b * CIN + ci) * HW);
        float m[3][4];
        #pragma unroll
        for (int r = 0; r < 3; r++) {
            int yy = h + r - 1;
            bool yok = (unsigned)yy < (unsigned)H_;
            #pragma unroll
            for (int c = 0; c < 4; c++) {
                int xx = w0 + c - 1;
                bool ok = yok && ((unsigned)xx < (unsigned)W_);
                m[r][c] = ok ? __ldg(xp + yy * W_ + xx) : 0.f;
            }
        }
        #pragma unroll
        for (int k = 0; k < 9; k++) {
            int ky = k / 3, kx = k % 3;
            ull vp0 = pack2(m[ky][kx],     m[ky][kx]);
            ull vp1 = pack2(m[ky][kx + 1], m[ky][kx + 1]);
            const ull* wq = (const ull*)(ws + (ci * 9 + k) * 10);
            #pragma unroll
            for (int j = 0; j < 5; j++) {
                ull q = wq[j];
                FMA2(acc0[j], vp0, q);
                FMA2(acc1[j], vp1, q);
            }
        }
    }

    int base = b * 9 * HW + h * W_ + w0;
    float r0[10], r1[10];
    #pragma unroll
    for (int j = 0; j < 5; j++) {
        unpack2(acc0[j], r0[2 * j], r0[2 * j + 1]);
        unpack2(acc1[j], r1[2 * j], r1[2 * j + 1]);
    }
    #pragma unroll
    for (int co = 0; co < 9; co++) {
        float s0 = r0[co] + bs[co];
        float s1 = r1[co] + bs[co];
        mask_buf[base + co * HW]     = 1.f / (1.f + expf(-s0));
        mask_buf[base + co * HW + 1] = 1.f / (1.f + expf(-s1));
    }
}

// ---------------- Kernel E: deformable conv as tiled GEMM ------------------
// grid = BATCH * (HW/128) blocks, 256 threads.
// Tile: 128 px x 64 co. K = 9 kernel taps x 64 cin, ci-chunks of 16.
// Each thread owns 8 px x 4 co fp32 accumulators.
#define DPX   128
#define APAD  132          // 128 + 4 floats, keeps 16B alignment (132*4=528)
#define NCHK  (HW / DPX)   // 240 chunks per image
__global__ void __launch_bounds__(256) deform_kernel(const float* __restrict__ x,
    const float* __restrict__ bias, float* __restrict__ out)
{
    __shared__ float Bs[64 * 64];        // W_k [ci][co]        16 KB
    __shared__ float As[16 * APAD];      // V  [ci_local][px]   8.25 KB
    __shared__ int   s_idx[4][DPX];      // bilinear tap indices
    __shared__ float s_wt[4][DPX];       // bilinear tap weights (mask folded)

    int tid    = threadIdx.x;
    int b      = blockIdx.x / NCHK;
    int pxbase = (blockIdx.x % NCHK) * DPX;

    const float* xb   = x + (size_t)(b * CIN * HW);
    const float* offb = off_buf + (size_t)(b * 18 * HW) + pxbase;
    const float* mb   = mask_buf + (size_t)(b * 9 * HW) + pxbase;

    // thread tile: 4 couts, 8 px
    int co0  = (tid & 15) * 4;
    int px0m = (tid >> 4) * 8;
    int gpx  = tid & 127;            // gather: this thread's pixel
    int cig0 = (tid >> 7) * 8;       // gather: first of 8 ci_locals

    float acc[8][4];
    #pragma unroll
    for (int i = 0; i < 8; i++) {
        #pragma unroll
        for (int j = 0; j < 4; j++) acc[i][j] = __ldg(bias + co0 + j);
    }

    for (int k = 0; k < 9; k++) {
        __syncthreads();   // protect Bs/desc from previous iteration's readers

        // stage W_k: [ci][co], coalesced from pre-transposed global
        {
            const float4* src = (const float4*)(convw_t + k * 4096);
            float4* dst = (float4*)Bs;
            #pragma unroll
            for (int r = 0; r < 4; r++)
                dst[r * 256 + tid] = src[r * 256 + tid];
        }

        // compute bilinear tap descriptors: one px per thread (tid < 128)
        if (tid < DPX) {
            int p = pxbase + tid;
            int h = p / W_;
            int w = p - h * W_;
            float dy = __ldg(offb + (k * 2 + 0) * HW + tid);
            float dx = __ldg(offb + (k * 2 + 1) * HW + tid);
            float mm = __ldg(mb + k * HW + tid);

            float ys = (float)(h + k / 3 - 1) + dy;
            float xs = (float)(w + k % 3 - 1) + dx;
            float fy = floorf(ys), fx = floorf(xs);
            int y0 = (int)fy, x0 = (int)fx;
            float wy = ys - fy, wx = xs - fx;

            bool vy0 = (unsigned)y0 < (unsigned)H_;
            bool vy1 = (unsigned)(y0 + 1) < (unsigned)H_;
            bool vx0 = (unsigned)x0 < (unsigned)W_;
            bool vx1 = (unsigned)(x0 + 1) < (unsigned)W_;

            int y0c = min(max(y0, 0), H_ - 1);
            int y1c = min(max(y0 + 1, 0), H_ - 1);
            int x0c = min(max(x0, 0), W_ - 1);
            int x1c = min(max(x0 + 1, 0), W_ - 1);

            s_idx[0][tid] = y0c * W_ + x0c;
            s_idx[1][tid] = y0c * W_ + x1c;
            s_idx[2][tid] = y1c * W_ + x0c;
            s_idx[3][tid] = y1c * W_ + x1c;
            s_wt[0][tid] = (vy0 && vx0) ? (1.f - wy) * (1.f - wx) * mm : 0.f;
            s_wt[1][tid] = (vy0 && vx1) ? (1.f - wy) * wx * mm : 0.f;
            s_wt[2][tid] = (vy1 && vx0) ? wy * (1.f - wx) * mm : 0.f;
            s_wt[3][tid] = (vy1 && vx1) ? wy * wx * mm : 0.f;
        }
        __syncthreads();

        // this thread's pixel descriptors (reused for all its ci)
        int   i0 = s_idx[0][gpx], i1 = s_idx[1][gpx];
        int   i2 = s_idx[2][gpx], i3 = s_idx[3][gpx];
        float t0 = s_wt[0][gpx],  t1 = s_wt[1][gpx];
        float t2 = s_wt[2][gpx],  t3 = s_wt[3][gpx];

        for (int cig = 0; cig < 4; cig++) {
            __syncthreads();   // protect As from previous math phase

            // gather: 8 ci for this thread's pixel
            #pragma unroll
            for (int j = 0; j < 8; j++) {
                int cl = cig0 + j;
                const float* xc = xb + (size_t)((cig * 16 + cl) * HW);
                float v = t0 * __ldg(xc + i0);
                v = fmaf(t1, __ldg(xc + i1), v);
                v = fmaf(t2, __ldg(xc + i2), v);
                v = fmaf(t3, __ldg(xc + i3), v);
                As[cl * APAD + gpx] = v;
            }
            __syncthreads();

            // math: 16 ci x (8 px x 4 co)
            const float* brow = Bs + cig * 16 * 64;
            #pragma unroll 4
            for (int ci = 0; ci < 16; ci++) {
                float4 b4 = *(const float4*)(brow + ci * 64 + co0);
                float4 a0 = *(const float4*)(As + ci * APAD + px0m);
                float4 a1 = *(const float4*)(As + ci * APAD + px0m + 4);
                float av[8] = {a0.x, a0.y, a0.z, a0.w, a1.x, a1.y, a1.z, a1.w};
                #pragma unroll
                for (int i = 0; i < 8; i++) {
                    acc[i][0] = fmaf(av[i], b4.x, acc[i][0]);
                    acc[i][1] = fmaf(av[i], b4.y, acc[i][1]);
                    acc[i][2] = fmaf(av[i], b4.z, acc[i][2]);
                    acc[i][3] = fmaf(av[i], b4.w, acc[i][3]);
                }
            }
        }
    }

    // write out: 4 couts x 8 px (two float4 per cout)
    float* ob = out + (size_t)(b * COUT * HW) + pxbase + px0m;
    #pragma unroll
    for (int j = 0; j < 4; j++) {
        float4 v0 = make_float4(acc[0][j], acc[1][j], acc[2][j], acc[3][j]);
        float4 v1 = make_float4(acc[4][j], acc[5][j], acc[6][j], acc[7][j]);
        *(float4*)(ob + (size_t)(co0 + j) * HW)     = v0;
        *(float4*)(ob + (size_t)(co0 + j) * HW + 4) = v1;
    }
}

// ---------------- launch ----------------------------------------------------
extern "C" void kernel_launch(void* const* d_in, const int* in_sizes, int n_in,
                              void* d_out, int out_size)
{
    const float* x        = (const float*)d_in[0];
    const float* scale    = (const float*)d_in[1];
    const float* glob_w1  = (const float*)d_in[2];
    const float* glob_b1  = (const float*)d_in[3];
    const float* glob_w2  = (const float*)d_in[4];
    const float* glob_b2  = (const float*)d_in[5];
    const float* loc_w1   = (const float*)d_in[6];
    const float* loc_b1   = (const float*)d_in[7];
    const float* loc_w2   = (const float*)d_in[8];
    const float* loc_b2   = (const float*)d_in[9];
    const float* fuse_w1  = (const float*)d_in[10];
    const float* fuse_b1  = (const float*)d_in[11];
    const float* fuse_w2  = (const float*)d_in[12];
    const float* fuse_b2  = (const float*)d_in[13];
    const float* mask_w   = (const float*)d_in[14];
    const float* mask_b   = (const float*)d_in[15];
    const float* conv_w   = (const float*)d_in[16];
    const float* conv_b   = (const float*)d_in[17];
    float* out = (float*)d_out;

    prep_kernel<<<(9 * 64 * 64 + 255) / 256, 256>>>(conv_w);
    g_kernel<<<1, 128>>>(scale, glob_w1, glob_b1, glob_w2, glob_b2);
    loc_kernel<<<BATCH * H_, 160>>>(x, loc_w1, loc_b1, loc_w2, loc_b2);
    mask_kernel<<<BATCH * H_, 160>>>(x, mask_w, mask_b);
    fuse_kernel<<<BATCH * H_, 160>>>(fuse_w1, fuse_b1, fuse_w2, fuse_b2);
    deform_kernel<<<BATCH * NCHK, 256>>>(x, conv_b, out);
}